// round 3
// baseline (speedup 1.0000x reference)
#include <cuda_runtime.h>
#include <math.h>

#define DIM   768
#define BATCH 16
#define SEQ   1024
#define MTOK  (BATCH * SEQ)   // 16384
#define EPS   1e-5f

// ---------------- scratch (static device globals: allocation-guard safe) ----
__device__ float g_Q[MTOK * DIM];
__device__ float g_KA[MTOK * DIM];
__device__ float g_KB[MTOK * DIM];
__device__ float g_VA[MTOK * DIM];
__device__ float g_VB[MTOK * DIM];
__device__ float g_S[(size_t)BATCH * SEQ * SEQ];
__device__ float g_interp[MTOK * DIM];
__device__ float g_h[MTOK * DIM];

// ---------------- SGEMM ----------------------------------------------------
// C[m,n] = alpha * sum_k A[m,k] * Bop[k,n]  (+ bias[n]) (+ C[m,n] if ACCUM)
//   A is row-major M x K (lda = K).
//   B_KN == false : B is row-major N x K (ldb = K), Bop = B^T  ("TN", dot-product)
//   B_KN == true  : B is row-major K x N (ldb = N), Bop = B    ("NN")
// Requires M%128==0, N%128==0, K%16==0 (true for every call here).
#define BM 128
#define BN 128
#define BKT 16

template <bool B_KN, bool ACCUM, bool BIAS>
__global__ __launch_bounds__(256)
void sgemm_kernel(int M, int N, int K, float alpha,
                  const float* __restrict__ A, int lda, long sA,
                  const float* __restrict__ B, int ldb, long sB,
                  const float* __restrict__ bias,
                  float* __restrict__ C, int ldc, long sC)
{
    const int bz = blockIdx.z;
    A += (size_t)bz * sA;
    B += (size_t)bz * sB;
    C += (size_t)bz * sC;

    const int m0 = blockIdx.y * BM;
    const int n0 = blockIdx.x * BN;
    const int tx = threadIdx.x;

    __shared__ float As[BKT][BM];
    __shared__ float Bs[BKT][BN];

    const int trow = tx >> 4;   // 0..15
    const int tcol = tx & 15;   // 0..15

    float acc[8][8];
#pragma unroll
    for (int i = 0; i < 8; i++)
#pragma unroll
        for (int j = 0; j < 8; j++) acc[i][j] = 0.0f;

    for (int k0 = 0; k0 < K; k0 += BKT) {
        // ---- load A tile (BM x BKT), store transposed -> As[k][m]
        {
            int f = tx;
#pragma unroll
            for (int it = 0; it < 2; ++it, f += 256) {
                int row = f >> 2;            // 0..127
                int kc  = (f & 3) << 2;      // 0,4,8,12
                float4 v = *(const float4*)(A + (size_t)(m0 + row) * lda + k0 + kc);
                As[kc + 0][row] = v.x;
                As[kc + 1][row] = v.y;
                As[kc + 2][row] = v.z;
                As[kc + 3][row] = v.w;
            }
        }
        // ---- load B tile
        if (!B_KN) {
            int f = tx;
#pragma unroll
            for (int it = 0; it < 2; ++it, f += 256) {
                int row = f >> 2;            // n index 0..127
                int kc  = (f & 3) << 2;
                float4 v = *(const float4*)(B + (size_t)(n0 + row) * ldb + k0 + kc);
                Bs[kc + 0][row] = v.x;
                Bs[kc + 1][row] = v.y;
                Bs[kc + 2][row] = v.z;
                Bs[kc + 3][row] = v.w;
            }
        } else {
            int f = tx;
#pragma unroll
            for (int it = 0; it < 2; ++it, f += 256) {
                int kk = f >> 5;             // 0..15
                int nc = (f & 31) << 2;      // 0..124
                float4 v = *(const float4*)(B + (size_t)(k0 + kk) * ldb + n0 + nc);
                *(float4*)&Bs[kk][nc] = v;
            }
        }
        __syncthreads();

#pragma unroll
        for (int k = 0; k < BKT; ++k) {
            float4 a0 = *(const float4*)&As[k][trow * 8];
            float4 a1 = *(const float4*)&As[k][trow * 8 + 4];
            float4 b0 = *(const float4*)&Bs[k][tcol * 8];
            float4 b1 = *(const float4*)&Bs[k][tcol * 8 + 4];
            float ar[8] = {a0.x, a0.y, a0.z, a0.w, a1.x, a1.y, a1.z, a1.w};
            float br[8] = {b0.x, b0.y, b0.z, b0.w, b1.x, b1.y, b1.z, b1.w};
#pragma unroll
            for (int i = 0; i < 8; i++)
#pragma unroll
                for (int j = 0; j < 8; j++)
                    acc[i][j] = fmaf(ar[i], br[j], acc[i][j]);
        }
        __syncthreads();
    }

    // ---- epilogue
#pragma unroll
    for (int i = 0; i < 8; i++) {
        int cm = m0 + trow * 8 + i;
        float* crow = C + (size_t)cm * ldc + n0 + tcol * 8;
#pragma unroll
        for (int j4 = 0; j4 < 2; j4++) {
            float4 v;
            v.x = acc[i][j4 * 4 + 0] * alpha;
            v.y = acc[i][j4 * 4 + 1] * alpha;
            v.z = acc[i][j4 * 4 + 2] * alpha;
            v.w = acc[i][j4 * 4 + 3] * alpha;
            if (BIAS) {
                const float* bp = bias + n0 + tcol * 8 + j4 * 4;
                v.x += bp[0]; v.y += bp[1]; v.z += bp[2]; v.w += bp[3];
            }
            if (ACCUM) {
                float4 o = *(float4*)(crow + j4 * 4);
                v.x += o.x; v.y += o.y; v.z += o.z; v.w += o.w;
            }
            *(float4*)(crow + j4 * 4) = v;
        }
    }
}

// ---------------- row softmax over SEQ=1024 (in place) ----------------------
__global__ __launch_bounds__(256)
void softmax_kernel(float* __restrict__ S)
{
    __shared__ float red[8];
    float* row = S + (size_t)blockIdx.x * SEQ;
    const int t = threadIdx.x;

    float4 v = ((float4*)row)[t];
    float m = fmaxf(fmaxf(v.x, v.y), fmaxf(v.z, v.w));
#pragma unroll
    for (int o = 16; o; o >>= 1) m = fmaxf(m, __shfl_xor_sync(0xffffffffu, m, o));
    if ((t & 31) == 0) red[t >> 5] = m;
    __syncthreads();
    float bmax = red[0];
#pragma unroll
    for (int i = 1; i < 8; i++) bmax = fmaxf(bmax, red[i]);
    __syncthreads();

    v.x = __expf(v.x - bmax);
    v.y = __expf(v.y - bmax);
    v.z = __expf(v.z - bmax);
    v.w = __expf(v.w - bmax);
    float s = v.x + v.y + v.z + v.w;
#pragma unroll
    for (int o = 16; o; o >>= 1) s += __shfl_xor_sync(0xffffffffu, s, o);
    if ((t & 31) == 0) red[t >> 5] = s;
    __syncthreads();
    float total = 0.0f;
#pragma unroll
    for (int i = 0; i < 8; i++) total += red[i];
    float inv = __frcp_rn(total);

    v.x *= inv; v.y *= inv; v.z *= inv; v.w *= inv;
    ((float4*)row)[t] = v;
}

// ---------------- h = LayerNorm(interp + x_C) * gamma + beta ----------------
__global__ __launch_bounds__(256)
void add_ln_kernel(const float* __restrict__ interp, const float* __restrict__ xC,
                   const float* __restrict__ gamma, const float* __restrict__ beta,
                   float* __restrict__ h)
{
    __shared__ float rs[8], rs2[8];
    const size_t base = (size_t)blockIdx.x * DIM;
    const int t = threadIdx.x;

    float x0 = interp[base + t]       + xC[base + t];
    float x1 = interp[base + t + 256] + xC[base + t + 256];
    float x2 = interp[base + t + 512] + xC[base + t + 512];

    float s  = x0 + x1 + x2;
    float ss = x0 * x0 + x1 * x1 + x2 * x2;
#pragma unroll
    for (int o = 16; o; o >>= 1) {
        s  += __shfl_xor_sync(0xffffffffu, s,  o);
        ss += __shfl_xor_sync(0xffffffffu, ss, o);
    }
    if ((t & 31) == 0) { rs[t >> 5] = s; rs2[t >> 5] = ss; }
    __syncthreads();
    float S1 = 0.0f, S2 = 0.0f;
#pragma unroll
    for (int i = 0; i < 8; i++) { S1 += rs[i]; S2 += rs2[i]; }

    const float mu   = S1 * (1.0f / DIM);
    const float var  = S2 * (1.0f / DIM) - mu * mu;
    const float rstd = rsqrtf(var + EPS);

    h[base + t]       = (x0 - mu) * rstd * gamma[t]       + beta[t];
    h[base + t + 256] = (x1 - mu) * rstd * gamma[t + 256] + beta[t + 256];
    h[base + t + 512] = (x2 - mu) * rstd * gamma[t + 512] + beta[t + 512];
}

// ---------------- launch ----------------------------------------------------
extern "C" void kernel_launch(void* const* d_in, const int* in_sizes, int n_in,
                              void* d_out, int out_size)
{
    const float* xA    = (const float*)d_in[0];
    const float* xB    = (const float*)d_in[1];
    const float* xC    = (const float*)d_in[2];
    const float* Wq    = (const float*)d_in[3];
    const float* bq    = (const float*)d_in[4];
    const float* Wk    = (const float*)d_in[5];
    const float* bk    = (const float*)d_in[6];
    const float* Wv    = (const float*)d_in[7];
    const float* bv    = (const float*)d_in[8];
    const float* gamma = (const float*)d_in[9];
    const float* beta  = (const float*)d_in[10];
    const float* Wfc   = (const float*)d_in[11];
    const float* bfc   = (const float*)d_in[12];
    float* out = (float*)d_out;

    float *Q, *KA, *KB, *VA, *VB, *Sb, *interp, *h;
    cudaGetSymbolAddress((void**)&Q,      g_Q);
    cudaGetSymbolAddress((void**)&KA,     g_KA);
    cudaGetSymbolAddress((void**)&KB,     g_KB);
    cudaGetSymbolAddress((void**)&VA,     g_VA);
    cudaGetSymbolAddress((void**)&VB,     g_VB);
    cudaGetSymbolAddress((void**)&Sb,     g_S);
    cudaGetSymbolAddress((void**)&interp, g_interp);
    cudaGetSymbolAddress((void**)&h,      g_h);

    const float scale = 1.0f / sqrtf((float)DIM);
    const dim3 blk(256);
    const dim3 gproj(DIM / BN, MTOK / BM, 1);          // 6 x 128
    const dim3 gscore(SEQ / BN, SEQ / BM, BATCH);      // 8 x 8 x 16
    const dim3 gav(DIM / BN, SEQ / BM, BATCH);         // 6 x 8 x 16
    const long sQK = (long)SEQ * DIM;
    const long sSS = (long)SEQ * SEQ;

    // projections: X @ W^T + b
    sgemm_kernel<false, false, true><<<gproj, blk>>>(MTOK, DIM, DIM, 1.0f,
        xC, DIM, 0, Wq, DIM, 0, bq, Q, DIM, 0);
    sgemm_kernel<false, false, true><<<gproj, blk>>>(MTOK, DIM, DIM, 1.0f,
        xA, DIM, 0, Wk, DIM, 0, bk, KA, DIM, 0);
    sgemm_kernel<false, false, true><<<gproj, blk>>>(MTOK, DIM, DIM, 1.0f,
        xB, DIM, 0, Wk, DIM, 0, bk, KB, DIM, 0);
    sgemm_kernel<false, false, true><<<gproj, blk>>>(MTOK, DIM, DIM, 1.0f,
        xA, DIM, 0, Wv, DIM, 0, bv, VA, DIM, 0);
    sgemm_kernel<false, false, true><<<gproj, blk>>>(MTOK, DIM, DIM, 1.0f,
        xB, DIM, 0, Wv, DIM, 0, bv, VB, DIM, 0);

    // branch A: S = softmax(scale * Q K^T); interp = S @ V_A
    sgemm_kernel<false, false, false><<<gscore, blk>>>(SEQ, SEQ, DIM, scale,
        Q, DIM, sQK, KA, DIM, sQK, nullptr, Sb, SEQ, sSS);
    softmax_kernel<<<BATCH * SEQ, blk>>>(Sb);
    sgemm_kernel<true, false, false><<<gav, blk>>>(SEQ, DIM, SEQ, 1.0f,
        Sb, SEQ, sSS, VA, DIM, sQK, nullptr, interp, DIM, sQK);

    // branch B: accumulate
    sgemm_kernel<false, false, false><<<gscore, blk>>>(SEQ, SEQ, DIM, scale,
        Q, DIM, sQK, KB, DIM, sQK, nullptr, Sb, SEQ, sSS);
    softmax_kernel<<<BATCH * SEQ, blk>>>(Sb);
    sgemm_kernel<true, true, false><<<gav, blk>>>(SEQ, DIM, SEQ, 1.0f,
        Sb, SEQ, sSS, VB, DIM, sQK, nullptr, interp, DIM, sQK);

    // h = LN(interp + x_C); out = h @ Wfc^T + bfc
    add_ln_kernel<<<MTOK, blk>>>(interp, xC, gamma, beta, h);
    sgemm_kernel<false, false, true><<<gproj, blk>>>(MTOK, DIM, DIM, 1.0f,
        h, DIM, 0, Wfc, DIM, 0, bfc, out, DIM, 0);
}

// round 5
// speedup vs baseline: 2.5359x; 2.5359x over previous
#include <cuda_runtime.h>
#include <cuda_bf16.h>
#include <math.h>
#include <stdint.h>

#define DIM    768
#define BATCH  16
#define SEQ    1024
#define MTOK   (BATCH * SEQ)      // 16384
#define KE_PROJ (3 * DIM)         // 2304 (extended K for split-bf16)
#define KE_ATT  (3 * SEQ)         // 3072
#define EPS    1e-5f

// ---------------------------------------------------------------------------
// Scratch (__device__ globals: allocation-guard safe)
// ---------------------------------------------------------------------------
__device__ __nv_bfloat16 g_xAe[(size_t)MTOK * KE_PROJ];
__device__ __nv_bfloat16 g_xBe[(size_t)MTOK * KE_PROJ];
__device__ __nv_bfloat16 g_xCe[(size_t)MTOK * KE_PROJ];
__device__ __nv_bfloat16 g_Wqe[(size_t)DIM * KE_PROJ];
__device__ __nv_bfloat16 g_Wke[(size_t)DIM * KE_PROJ];
__device__ __nv_bfloat16 g_Wve[(size_t)DIM * KE_PROJ];
__device__ __nv_bfloat16 g_Wfce[(size_t)DIM * KE_PROJ];
__device__ float g_Q [(size_t)MTOK * DIM];
__device__ float g_KA[(size_t)MTOK * DIM];
__device__ float g_KB[(size_t)MTOK * DIM];
__device__ float g_VA[(size_t)MTOK * DIM];
__device__ float g_VB[(size_t)MTOK * DIM];
__device__ __nv_bfloat16 g_Qe [(size_t)MTOK * KE_PROJ];
__device__ __nv_bfloat16 g_KAe[(size_t)MTOK * KE_PROJ];
__device__ __nv_bfloat16 g_KBe[(size_t)MTOK * KE_PROJ];
__device__ __nv_bfloat16 g_VtAe[(size_t)BATCH * DIM * KE_ATT];
__device__ __nv_bfloat16 g_VtBe[(size_t)BATCH * DIM * KE_ATT];
__device__ float g_S[(size_t)BATCH * SEQ * SEQ];
__device__ __nv_bfloat16 g_Se[(size_t)BATCH * SEQ * KE_ATT];
__device__ float g_iA[(size_t)MTOK * DIM];
__device__ float g_iB[(size_t)MTOK * DIM];
__device__ __nv_bfloat16 g_he[(size_t)MTOK * KE_PROJ];

// ---------------------------------------------------------------------------
// helpers
// ---------------------------------------------------------------------------
__device__ __forceinline__ uint32_t smem_u32(const void* p) {
    uint32_t a;
    asm("{ .reg .u64 t; cvta.to.shared.u64 t, %1; cvt.u32.u64 %0, t; }"
        : "=r"(a) : "l"(p));
    return a;
}
__device__ __forceinline__ uint32_t swz(uint32_t off) {
    return off ^ ((off >> 3) & 0x70);   // SW128: XOR bits[4:6] with row bits[7:9]
}
__device__ __forceinline__ void cp_async16(uint32_t dst, const void* src) {
    asm volatile("cp.async.cg.shared.global [%0], [%1], 16;"
                 :: "r"(dst), "l"(src) : "memory");
}
__device__ __forceinline__ void cp_commit() {
    asm volatile("cp.async.commit_group;" ::: "memory");
}
__device__ __forceinline__ void cp_wait1() {
    asm volatile("cp.async.wait_group 1;" ::: "memory");
}
__device__ __forceinline__ void ldsm_x4(uint32_t addr, uint32_t& r0, uint32_t& r1,
                                        uint32_t& r2, uint32_t& r3) {
    asm volatile("ldmatrix.sync.aligned.m8n8.x4.shared.b16 {%0,%1,%2,%3}, [%4];"
                 : "=r"(r0), "=r"(r1), "=r"(r2), "=r"(r3) : "r"(addr));
}
__device__ __forceinline__ void mma16816(float* c, const uint32_t* a,
                                         uint32_t b0, uint32_t b1) {
    asm volatile(
        "mma.sync.aligned.m16n8k16.row.col.f32.bf16.bf16.f32 "
        "{%0,%1,%2,%3}, {%4,%5,%6,%7}, {%8,%9}, {%0,%1,%2,%3};"
        : "+f"(c[0]), "+f"(c[1]), "+f"(c[2]), "+f"(c[3])
        : "r"(a[0]), "r"(a[1]), "r"(a[2]), "r"(a[3]), "r"(b0), "r"(b1));
}

// ---------------------------------------------------------------------------
// bf16 TN GEMM via mma.sync:  C[M,N] = alpha * A[M,Kext] · B[N,Kext]^T (+bias)
// BM=128, BN=128, BK=64.  8 warps, each computes 64x32.
// cp.async double-buffered smem (2 x 32KB), SW128 swizzle, ldmatrix.x4 loads.
// grid = (N/128, M/128, batch), block = 256, dyn smem = 64KB.
// ---------------------------------------------------------------------------
#define GBM 128
#define GBN 128
#define GBK 64
#define TILE_AB 32768          // A(16KB)+B(16KB) per buffer
#define GEMM_SMEM (2 * TILE_AB)

__global__ __launch_bounds__(256)
void gemm_bf16s(const __nv_bfloat16* __restrict__ A, long sA,
                const __nv_bfloat16* __restrict__ B, long sB,
                int Kext,
                float* __restrict__ C, int ldc, long sC,
                const float* __restrict__ bias, float alpha)
{
    extern __shared__ char smem[];
    const uint32_t sbase = smem_u32(smem);
    const int tid  = threadIdx.x;
    const int wid  = tid >> 5;
    const int lane = tid & 31;
    const int warp_m = wid >> 2;      // 0..1
    const int warp_n = wid & 3;       // 0..3

    A += (size_t)blockIdx.z * sA;
    B += (size_t)blockIdx.z * sB;
    C += (size_t)blockIdx.z * sC;
    const int m0 = blockIdx.y * GBM;
    const int n0 = blockIdx.x * GBN;

    const int row_ld = tid >> 3;           // 0..127 (16B chunk loader mapping)
    const int cg_ld  = tid & 7;            // 0..7
    const uint32_t st_off = swz(row_ld * 128 + cg_ld * 16);

    const int nch = Kext / GBK;

    // issue cp.async for tile c into buffer c&1
    auto issue_tile = [&](int c) {
        const __nv_bfloat16* Ak = A + (size_t)c * GBK;
        const __nv_bfloat16* Bk = B + (size_t)c * GBK;
        const uint32_t abase = sbase + (uint32_t)(c & 1) * TILE_AB;
        const uint32_t bbase = abase + 16384;
#pragma unroll
        for (int i = 0; i < 4; ++i) {
            int row = row_ld + i * 32;
            uint32_t off = swz(row * 128 + cg_ld * 16);
            cp_async16(abase + off, Ak + (size_t)(m0 + row) * Kext + cg_ld * 8);
        }
#pragma unroll
        for (int i = 0; i < 4; ++i) {
            int row = row_ld + i * 32;
            uint32_t off = swz(row * 128 + cg_ld * 16);
            cp_async16(bbase + off, Bk + (size_t)(n0 + row) * Kext + cg_ld * 8);
        }
    };
    (void)st_off;

    float acc[4][4][4];
#pragma unroll
    for (int i = 0; i < 4; ++i)
#pragma unroll
        for (int j = 0; j < 4; ++j)
#pragma unroll
            for (int k = 0; k < 4; ++k) acc[i][j][k] = 0.0f;

    issue_tile(0); cp_commit();
    issue_tile(1); cp_commit();

    // per-lane ldmatrix base offsets (within a buffer)
    const uint32_t a_lane = (uint32_t)(warp_m * 64 + (lane & 15)) * 128
                          + (uint32_t)(lane >> 4) * 16;
    const uint32_t b_lane = (uint32_t)(warp_n * 32 + (lane & 15)) * 128
                          + (uint32_t)(lane >> 4) * 16;

    for (int c = 0; c < nch; ++c) {
        cp_wait1();
        __syncthreads();
        const uint32_t abase = sbase + (uint32_t)(c & 1) * TILE_AB;
        const uint32_t bbase = abase + 16384;

#pragma unroll
        for (int ks = 0; ks < 4; ++ks) {
            uint32_t a[4][4];
            uint32_t b[2][4];
#pragma unroll
            for (int mi = 0; mi < 4; ++mi)
                ldsm_x4(abase + swz(a_lane + mi * 16 * 128 + ks * 32),
                        a[mi][0], a[mi][1], a[mi][2], a[mi][3]);
#pragma unroll
            for (int nj = 0; nj < 2; ++nj)
                ldsm_x4(bbase + swz(b_lane + nj * 16 * 128 + ks * 32),
                        b[nj][0], b[nj][1], b[nj][2], b[nj][3]);
#pragma unroll
            for (int mi = 0; mi < 4; ++mi) {
#pragma unroll
                for (int nj = 0; nj < 2; ++nj) {
                    mma16816(acc[mi][nj * 2 + 0], a[mi], b[nj][0], b[nj][2]);
                    mma16816(acc[mi][nj * 2 + 1], a[mi], b[nj][1], b[nj][3]);
                }
            }
        }
        __syncthreads();
        if (c + 2 < nch) issue_tile(c + 2);
        cp_commit();
    }

    // ---- epilogue
#pragma unroll
    for (int mi = 0; mi < 4; ++mi) {
        const int row = m0 + warp_m * 64 + mi * 16 + (lane >> 2);
#pragma unroll
        for (int nf = 0; nf < 4; ++nf) {
            const int col = n0 + warp_n * 32 + nf * 8 + (lane & 3) * 2;
            float bx = 0.0f, by = 0.0f;
            if (bias) { bx = bias[col]; by = bias[col + 1]; }
            float2 v0, v1;
            v0.x = acc[mi][nf][0] * alpha + bx;
            v0.y = acc[mi][nf][1] * alpha + by;
            v1.x = acc[mi][nf][2] * alpha + bx;
            v1.y = acc[mi][nf][3] * alpha + by;
            *(float2*)(C + (size_t)row * ldc + col) = v0;
            *(float2*)(C + (size_t)(row + 8) * ldc + col) = v1;
        }
    }
}

// ---------------------------------------------------------------------------
// split helpers + conversion kernels
// ---------------------------------------------------------------------------
__device__ __forceinline__ void split1(float x, __nv_bfloat16& h, __nv_bfloat16& l) {
    h = __float2bfloat16(x);
    l = __float2bfloat16(x - __bfloat162float(h));
}

// fp32 [M,K] -> bf16 ext [M,3K].  AROLE: [hi|hi|lo].  !AROLE (B): [hi|lo|hi].
template <bool AROLE>
__global__ __launch_bounds__(256)
void split_kernel(const float* __restrict__ X, __nv_bfloat16* __restrict__ O, int K)
{
    const int p = blockIdx.x * 256 + threadIdx.x;   // pair index
    const int Kh = K >> 1;
    const int row = p / Kh;
    const int kk = (p - row * Kh) * 2;
    float2 x = *(const float2*)(X + (size_t)row * K + kk);
    __nv_bfloat16 h0, l0, h1, l1;
    split1(x.x, h0, l0);
    split1(x.y, h1, l1);
    __nv_bfloat162 H; H.x = h0; H.y = h1;
    __nv_bfloat162 L; L.x = l0; L.y = l1;
    __nv_bfloat162* o = (__nv_bfloat162*)(O + (size_t)row * 3 * K);
    const int k2 = kk >> 1, K2 = K >> 1;
    o[k2] = H;
    if (AROLE) { o[K2 + k2] = H; o[2 * K2 + k2] = L; }
    else       { o[K2 + k2] = L; o[2 * K2 + k2] = H; }
}

// V [B][S][D] fp32  ->  Vt ext [B][D][3S] bf16, B-role [hi|lo|hi], transposed.
__global__ __launch_bounds__(256)
void tsplit_kernel(const float* __restrict__ V, __nv_bfloat16* __restrict__ O)
{
    __shared__ float tile[32][33];
    const int tx = threadIdx.x, ty = threadIdx.y;
    const int k0 = blockIdx.y * 32, n0 = blockIdx.x * 32;
    const float* Vb = V + (size_t)blockIdx.z * SEQ * DIM;
#pragma unroll
    for (int j = 0; j < 4; ++j)
        tile[ty + j * 8][tx] = Vb[(size_t)(k0 + ty + j * 8) * DIM + n0 + tx];
    __syncthreads();
    __nv_bfloat16* Ob = O + (size_t)blockIdx.z * DIM * KE_ATT;
#pragma unroll
    for (int j = 0; j < 4; ++j) {
        const int n = n0 + ty + j * 8;
        const int k = k0 + tx;
        float x = tile[tx][ty + j * 8];
        __nv_bfloat16 h, l;
        split1(x, h, l);
        const size_t base = (size_t)n * KE_ATT;
        Ob[base + k] = h;
        Ob[base + SEQ + k] = l;
        Ob[base + 2 * SEQ + k] = h;
    }
}

// row softmax over SEQ=1024, fused output to bf16 ext (A-role [hi|hi|lo])
__global__ __launch_bounds__(256)
void softmax_split_kernel(const float* __restrict__ S, __nv_bfloat16* __restrict__ O)
{
    __shared__ float red[8];
    const float* row = S + (size_t)blockIdx.x * SEQ;
    const int t = threadIdx.x;

    float4 v = ((const float4*)row)[t];
    float m = fmaxf(fmaxf(v.x, v.y), fmaxf(v.z, v.w));
#pragma unroll
    for (int o = 16; o; o >>= 1) m = fmaxf(m, __shfl_xor_sync(0xffffffffu, m, o));
    if ((t & 31) == 0) red[t >> 5] = m;
    __syncthreads();
    float bmax = red[0];
#pragma unroll
    for (int i = 1; i < 8; i++) bmax = fmaxf(bmax, red[i]);
    __syncthreads();

    v.x = __expf(v.x - bmax); v.y = __expf(v.y - bmax);
    v.z = __expf(v.z - bmax); v.w = __expf(v.w - bmax);
    float s = v.x + v.y + v.z + v.w;
#pragma unroll
    for (int o = 16; o; o >>= 1) s += __shfl_xor_sync(0xffffffffu, s, o);
    if ((t & 31) == 0) red[t >> 5] = s;
    __syncthreads();
    float tot = 0.0f;
#pragma unroll
    for (int i = 0; i < 8; i++) tot += red[i];
    const float inv = __frcp_rn(tot);
    v.x *= inv; v.y *= inv; v.z *= inv; v.w *= inv;

    __nv_bfloat16 h0, l0, h1, l1, h2, l2, h3, l3;
    split1(v.x, h0, l0); split1(v.y, h1, l1);
    split1(v.z, h2, l2); split1(v.w, h3, l3);
    __nv_bfloat162 H0; H0.x = h0; H0.y = h1;
    __nv_bfloat162 H1; H1.x = h2; H1.y = h3;
    __nv_bfloat162 L0; L0.x = l0; L0.y = l1;
    __nv_bfloat162 L1; L1.x = l2; L1.y = l3;
    __nv_bfloat162* o = (__nv_bfloat162*)(O + (size_t)blockIdx.x * KE_ATT);
    const int k2 = t * 2;              // bf162 index of col t*4
    o[k2] = H0;                  o[k2 + 1] = H1;
    o[(SEQ >> 1) + k2] = H0;     o[(SEQ >> 1) + k2 + 1] = H1;
    o[SEQ + k2] = L0;            o[SEQ + k2 + 1] = L1;
}

// h = LN(iA + iB + xC) * gamma + beta, fused output to bf16 ext (A-role)
__global__ __launch_bounds__(256)
void add_ln_split_kernel(const float* __restrict__ iA, const float* __restrict__ iB,
                         const float* __restrict__ xC,
                         const float* __restrict__ gamma, const float* __restrict__ beta,
                         __nv_bfloat16* __restrict__ O)
{
    __shared__ float rs[8], rs2[8];
    const size_t base = (size_t)blockIdx.x * DIM;
    const int t = threadIdx.x;

    float x0 = iA[base + t]       + iB[base + t]       + xC[base + t];
    float x1 = iA[base + t + 256] + iB[base + t + 256] + xC[base + t + 256];
    float x2 = iA[base + t + 512] + iB[base + t + 512] + xC[base + t + 512];

    float s = x0 + x1 + x2;
    float ss = x0 * x0 + x1 * x1 + x2 * x2;
#pragma unroll
    for (int o = 16; o; o >>= 1) {
        s  += __shfl_xor_sync(0xffffffffu, s,  o);
        ss += __shfl_xor_sync(0xffffffffu, ss, o);
    }
    if ((t & 31) == 0) { rs[t >> 5] = s; rs2[t >> 5] = ss; }
    __syncthreads();
    float S1 = 0.0f, S2 = 0.0f;
#pragma unroll
    for (int i = 0; i < 8; i++) { S1 += rs[i]; S2 += rs2[i]; }
    const float mu = S1 * (1.0f / DIM);
    const float var = S2 * (1.0f / DIM) - mu * mu;
    const float rstd = rsqrtf(var + EPS);

    __nv_bfloat16* ob = O + (size_t)blockIdx.x * KE_PROJ;
#pragma unroll
    for (int e = 0; e < 3; ++e) {
        const int col = t + e * 256;
        const float x = (e == 0) ? x0 : (e == 1) ? x1 : x2;
        const float y = (x - mu) * rstd * gamma[col] + beta[col];
        __nv_bfloat16 h, l;
        split1(y, h, l);
        ob[col] = h;
        ob[DIM + col] = h;
        ob[2 * DIM + col] = l;
    }
}

// ---------------------------------------------------------------------------
// launch
// ---------------------------------------------------------------------------
extern "C" void kernel_launch(void* const* d_in, const int* in_sizes, int n_in,
                              void* d_out, int out_size)
{
    const float* xA    = (const float*)d_in[0];
    const float* xB    = (const float*)d_in[1];
    const float* xC    = (const float*)d_in[2];
    const float* Wq    = (const float*)d_in[3];
    const float* bq    = (const float*)d_in[4];
    const float* Wk    = (const float*)d_in[5];
    const float* bk    = (const float*)d_in[6];
    const float* Wv    = (const float*)d_in[7];
    const float* bv    = (const float*)d_in[8];
    const float* gamma = (const float*)d_in[9];
    const float* beta  = (const float*)d_in[10];
    const float* Wfc   = (const float*)d_in[11];
    const float* bfc   = (const float*)d_in[12];
    float* out = (float*)d_out;

    __nv_bfloat16 *xAe, *xBe, *xCe, *Wqe, *Wke, *Wve, *Wfce;
    __nv_bfloat16 *Qe, *KAe, *KBe, *VtAe, *VtBe, *Se, *he;
    float *Q, *KA, *KB, *VA, *VB, *Sf, *iA, *iB;
    cudaGetSymbolAddress((void**)&xAe, g_xAe);
    cudaGetSymbolAddress((void**)&xBe, g_xBe);
    cudaGetSymbolAddress((void**)&xCe, g_xCe);
    cudaGetSymbolAddress((void**)&Wqe, g_Wqe);
    cudaGetSymbolAddress((void**)&Wke, g_Wke);
    cudaGetSymbolAddress((void**)&Wve, g_Wve);
    cudaGetSymbolAddress((void**)&Wfce, g_Wfce);
    cudaGetSymbolAddress((void**)&Q,  g_Q);
    cudaGetSymbolAddress((void**)&KA, g_KA);
    cudaGetSymbolAddress((void**)&KB, g_KB);
    cudaGetSymbolAddress((void**)&VA, g_VA);
    cudaGetSymbolAddress((void**)&VB, g_VB);
    cudaGetSymbolAddress((void**)&Qe,  g_Qe);
    cudaGetSymbolAddress((void**)&KAe, g_KAe);
    cudaGetSymbolAddress((void**)&KBe, g_KBe);
    cudaGetSymbolAddress((void**)&VtAe, g_VtAe);
    cudaGetSymbolAddress((void**)&VtBe, g_VtBe);
    cudaGetSymbolAddress((void**)&Sf, g_S);
    cudaGetSymbolAddress((void**)&Se, g_Se);
    cudaGetSymbolAddress((void**)&iA, g_iA);
    cudaGetSymbolAddress((void**)&iB, g_iB);
    cudaGetSymbolAddress((void**)&he, g_he);

    cudaFuncSetAttribute(gemm_bf16s, cudaFuncAttributeMaxDynamicSharedMemorySize,
                         GEMM_SMEM);

    const float scale = 1.0f / sqrtf((float)DIM);
    const dim3 blk(256);

    // ---- operand conversions (inputs + weights)
    const int xblocks = MTOK * DIM / 2 / 256;      // 24576
    const int wblocks = DIM * DIM / 2 / 256;       // 1152
    split_kernel<true ><<<xblocks, blk>>>(xA, xAe, DIM);
    split_kernel<true ><<<xblocks, blk>>>(xB, xBe, DIM);
    split_kernel<true ><<<xblocks, blk>>>(xC, xCe, DIM);
    split_kernel<false><<<wblocks, blk>>>(Wq, Wqe, DIM);
    split_kernel<false><<<wblocks, blk>>>(Wk, Wke, DIM);
    split_kernel<false><<<wblocks, blk>>>(Wv, Wve, DIM);
    split_kernel<false><<<wblocks, blk>>>(Wfc, Wfce, DIM);

    // ---- projections (M=16384, N=768, Kext=2304)
    const dim3 gproj(DIM / GBN, MTOK / GBM, 1);    // (6, 128)
    gemm_bf16s<<<gproj, blk, GEMM_SMEM>>>(xCe, 0, Wqe, 0, KE_PROJ, Q,  DIM, 0, bq, 1.0f);
    gemm_bf16s<<<gproj, blk, GEMM_SMEM>>>(xAe, 0, Wke, 0, KE_PROJ, KA, DIM, 0, bk, 1.0f);
    gemm_bf16s<<<gproj, blk, GEMM_SMEM>>>(xBe, 0, Wke, 0, KE_PROJ, KB, DIM, 0, bk, 1.0f);
    gemm_bf16s<<<gproj, blk, GEMM_SMEM>>>(xAe, 0, Wve, 0, KE_PROJ, VA, DIM, 0, bv, 1.0f);
    gemm_bf16s<<<gproj, blk, GEMM_SMEM>>>(xBe, 0, Wve, 0, KE_PROJ, VB, DIM, 0, bv, 1.0f);

    // ---- convert Q/K (row splits) and V (transpose splits)
    split_kernel<true ><<<xblocks, blk>>>(Q,  Qe,  DIM);
    split_kernel<false><<<xblocks, blk>>>(KA, KAe, DIM);
    split_kernel<false><<<xblocks, blk>>>(KB, KBe, DIM);
    const dim3 tblk(32, 8);
    const dim3 tgrid(DIM / 32, SEQ / 32, BATCH);   // (24, 32, 16)
    tsplit_kernel<<<tgrid, tblk>>>(VA, VtAe);
    tsplit_kernel<<<tgrid, tblk>>>(VB, VtBe);

    // ---- attention
    const dim3 gqk(SEQ / GBN, SEQ / GBM, BATCH);   // (8, 8, 16)
    const dim3 gpv(DIM / GBN, SEQ / GBM, BATCH);   // (6, 8, 16)
    const long sQK = (long)SEQ * KE_PROJ;
    const long sSS = (long)SEQ * SEQ;
    const long sSE = (long)SEQ * KE_ATT;
    const long sVT = (long)DIM * KE_ATT;
    const long sIO = (long)SEQ * DIM;

    gemm_bf16s<<<gqk, blk, GEMM_SMEM>>>(Qe, sQK, KAe, sQK, KE_PROJ, Sf, SEQ, sSS, nullptr, scale);
    softmax_split_kernel<<<BATCH * SEQ, blk>>>(Sf, Se);
    gemm_bf16s<<<gpv, blk, GEMM_SMEM>>>(Se, sSE, VtAe, sVT, KE_ATT, iA, DIM, sIO, nullptr, 1.0f);

    gemm_bf16s<<<gqk, blk, GEMM_SMEM>>>(Qe, sQK, KBe, sQK, KE_PROJ, Sf, SEQ, sSS, nullptr, scale);
    softmax_split_kernel<<<BATCH * SEQ, blk>>>(Sf, Se);
    gemm_bf16s<<<gpv, blk, GEMM_SMEM>>>(Se, sSE, VtBe, sVT, KE_ATT, iB, DIM, sIO, nullptr, 1.0f);

    // ---- residual + LN (fused split) + final FC
    add_ln_split_kernel<<<MTOK, blk>>>(iA, iB, xC, gamma, beta, he);
    gemm_bf16s<<<gproj, blk, GEMM_SMEM>>>(he, 0, Wfce, 0, KE_PROJ, out, DIM, 0, bfc, 1.0f);
}

// round 6
// speedup vs baseline: 3.7837x; 1.4921x over previous
#include <cuda_runtime.h>
#include <math.h>
#include <stdint.h>

#define DIM    768
#define BATCH  16
#define SEQ    1024
#define MTOK   (BATCH * SEQ)      // 16384
#define EPS    1e-5f

// ---------------------------------------------------------------------------
// Scratch (__device__ globals: allocation-guard safe)
// ---------------------------------------------------------------------------
__device__ float g_Q  [(size_t)MTOK * DIM];
__device__ float g_KA [(size_t)MTOK * DIM];
__device__ float g_KB [(size_t)MTOK * DIM];
__device__ float g_VA [(size_t)MTOK * DIM];
__device__ float g_VB [(size_t)MTOK * DIM];
__device__ float g_VtA[(size_t)BATCH * DIM * SEQ];
__device__ float g_VtB[(size_t)BATCH * DIM * SEQ];
__device__ float g_S  [(size_t)BATCH * SEQ * SEQ];
__device__ float g_iA [(size_t)MTOK * DIM];
__device__ float g_iB [(size_t)MTOK * DIM];
__device__ float g_h  [(size_t)MTOK * DIM];

// ---------------------------------------------------------------------------
// helpers
// ---------------------------------------------------------------------------
__device__ __forceinline__ uint32_t smem_u32(const void* p) {
    uint32_t a;
    asm("{ .reg .u64 t; cvta.to.shared.u64 t, %1; cvt.u32.u64 %0, t; }"
        : "=r"(a) : "l"(p));
    return a;
}
__device__ __forceinline__ uint32_t swz(uint32_t off) {
    return off ^ ((off >> 3) & 0x70);   // SW128 on 128B rows
}
__device__ __forceinline__ void cp_async16(uint32_t dst, const void* src) {
    asm volatile("cp.async.cg.shared.global [%0], [%1], 16;"
                 :: "r"(dst), "l"(src) : "memory");
}
__device__ __forceinline__ void cp_commit() {
    asm volatile("cp.async.commit_group;" ::: "memory");
}
template <int N>
__device__ __forceinline__ void cp_wait() {
    asm volatile("cp.async.wait_group %0;" :: "n"(N) : "memory");
}
__device__ __forceinline__ void ldsm_x4(uint32_t addr, uint32_t& r0, uint32_t& r1,
                                        uint32_t& r2, uint32_t& r3) {
    asm volatile("ldmatrix.sync.aligned.m8n8.x4.shared.b16 {%0,%1,%2,%3}, [%4];"
                 : "=r"(r0), "=r"(r1), "=r"(r2), "=r"(r3) : "r"(addr));
}
__device__ __forceinline__ uint32_t cvt_tf32(uint32_t x) {
    uint32_t y;
    asm("cvt.rna.tf32.f32 %0, %1;" : "=r"(y) : "r"(x));
    return y;
}
__device__ __forceinline__ void mma_tf32(float* c, const uint32_t* a,
                                         uint32_t b0, uint32_t b1) {
    asm volatile(
        "mma.sync.aligned.m16n8k8.row.col.f32.tf32.tf32.f32 "
        "{%0,%1,%2,%3}, {%4,%5,%6,%7}, {%8,%9}, {%0,%1,%2,%3};"
        : "+f"(c[0]), "+f"(c[1]), "+f"(c[2]), "+f"(c[3])
        : "r"(a[0]), "r"(a[1]), "r"(a[2]), "r"(a[3]), "r"(b0), "r"(b1));
}

// ---------------------------------------------------------------------------
// TF32 TN GEMM:  C[M,N] = alpha * A[M,K] · B[N,K]^T (+bias)
// A, B row-major, row stride == K.  BM=128, BN=256, BK=32 (128B rows).
// 8 warps (2x4), warp tile 64x64.  4-stage cp.async, SW128 swizzle, ldmatrix.
// grid = (N/256, M/128, batch), block = 256, dyn smem = 192KB, 1 CTA/SM.
// ---------------------------------------------------------------------------
#define GBM 128
#define GBN 256
#define GBK 32
#define A_STG (GBM * 128)          // 16384 B
#define B_STG (GBN * 128)          // 32768 B
#define STG   (A_STG + B_STG)      // 49152 B
#define NSTAGE 4
#define GEMM_SMEM (NSTAGE * STG)   // 196608 B

__global__ __launch_bounds__(256, 1)
void gemm_tf32(const float* __restrict__ A, long sA,
               const float* __restrict__ B, long sB,
               int K,
               float* __restrict__ C, int ldc, long sC,
               const float* __restrict__ bias, float alpha)
{
    extern __shared__ char smem[];
    const uint32_t sbase = smem_u32(smem);
    const int tid  = threadIdx.x;
    const int wid  = tid >> 5;
    const int lane = tid & 31;
    const int warp_m = wid >> 2;        // 0..1  (64 rows each)
    const int warp_n = wid & 3;         // 0..3  (64 cols each)

    A += (size_t)blockIdx.z * sA;
    B += (size_t)blockIdx.z * sB;
    C += (size_t)blockIdx.z * sC;
    const int m0 = blockIdx.y * GBM;
    const int n0 = blockIdx.x * GBN;

    const int ld_row = tid >> 3;        // 0..31
    const int ld_cg  = tid & 7;         // 16B chunk within 128B row

    auto issue = [&](int c) {
        const uint32_t abase = sbase + (uint32_t)(c & 3) * STG;
        const uint32_t bbase = abase + A_STG;
        const float* Ak = A + (size_t)c * GBK;
        const float* Bk = B + (size_t)c * GBK;
#pragma unroll
        for (int i = 0; i < 4; ++i) {
            int r = ld_row + i * 32;
            cp_async16(abase + swz(r * 128 + ld_cg * 16),
                       Ak + (size_t)(m0 + r) * K + ld_cg * 4);
        }
#pragma unroll
        for (int i = 0; i < 8; ++i) {
            int r = ld_row + i * 32;
            cp_async16(bbase + swz(r * 128 + ld_cg * 16),
                       Bk + (size_t)(n0 + r) * K + ld_cg * 4);
        }
    };

    float acc[4][8][4];
#pragma unroll
    for (int i = 0; i < 4; ++i)
#pragma unroll
        for (int j = 0; j < 8; ++j)
#pragma unroll
            for (int k = 0; k < 4; ++k) acc[i][j][k] = 0.0f;

    const int nch = K / GBK;
#pragma unroll
    for (int s = 0; s < NSTAGE; ++s) { issue(s); cp_commit(); }

    // per-lane ldmatrix address components (lane l supplies row l&7 of matrix l>>3)
    const int mat = lane >> 3, r8 = lane & 7;
    const uint32_t a_off0 = (uint32_t)(warp_m * 64 + (mat & 1) * 8 + r8) * 128
                          + (uint32_t)(mat >> 1) * 16;
    const uint32_t b_off0 = (uint32_t)(warp_n * 64 + (mat >> 1) * 8 + r8) * 128
                          + (uint32_t)(mat & 1) * 16;

    for (int c = 0; c < nch; ++c) {
        cp_wait<NSTAGE - 2>();
        __syncthreads();
        const uint32_t abase = sbase + (uint32_t)(c & 3) * STG;
        const uint32_t bbase = abase + A_STG;

#pragma unroll
        for (int ks = 0; ks < 4; ++ks) {
            uint32_t a[4][4], b[4][4];
#pragma unroll
            for (int mi = 0; mi < 4; ++mi) {
                ldsm_x4(abase + swz(a_off0 + mi * 16 * 128 + ks * 32),
                        a[mi][0], a[mi][1], a[mi][2], a[mi][3]);
#pragma unroll
                for (int q = 0; q < 4; ++q) a[mi][q] = cvt_tf32(a[mi][q]);
            }
#pragma unroll
            for (int nj = 0; nj < 4; ++nj) {
                ldsm_x4(bbase + swz(b_off0 + nj * 16 * 128 + ks * 32),
                        b[nj][0], b[nj][1], b[nj][2], b[nj][3]);
#pragma unroll
                for (int q = 0; q < 4; ++q) b[nj][q] = cvt_tf32(b[nj][q]);
            }
#pragma unroll
            for (int mi = 0; mi < 4; ++mi)
#pragma unroll
                for (int nj = 0; nj < 4; ++nj) {
                    mma_tf32(acc[mi][nj * 2 + 0], a[mi], b[nj][0], b[nj][1]);
                    mma_tf32(acc[mi][nj * 2 + 1], a[mi], b[nj][2], b[nj][3]);
                }
        }
        __syncthreads();
        if (c + NSTAGE < nch) issue(c + NSTAGE);
        cp_commit();
    }

    // ---- epilogue: warp writes its 64x64 tile
#pragma unroll
    for (int mi = 0; mi < 4; ++mi) {
        const int row = m0 + warp_m * 64 + mi * 16 + (lane >> 2);
#pragma unroll
        for (int nf = 0; nf < 8; ++nf) {
            const int col = n0 + warp_n * 64 + nf * 8 + (lane & 3) * 2;
            float bx = 0.0f, by = 0.0f;
            if (bias) { bx = bias[col]; by = bias[col + 1]; }
            float2 v0, v1;
            v0.x = acc[mi][nf][0] * alpha + bx;
            v0.y = acc[mi][nf][1] * alpha + by;
            v1.x = acc[mi][nf][2] * alpha + bx;
            v1.y = acc[mi][nf][3] * alpha + by;
            *(float2*)(C + (size_t)row * ldc + col) = v0;
            *(float2*)(C + (size_t)(row + 8) * ldc + col) = v1;
        }
    }
}

// ---------------------------------------------------------------------------
// V [B][S][D] -> Vt [B][D][S]  (fp32 transpose, 32x32 tiles)
// ---------------------------------------------------------------------------
__global__ __launch_bounds__(256)
void transpose_kernel(const float* __restrict__ V, float* __restrict__ O)
{
    __shared__ float tile[32][33];
    const int tx = threadIdx.x, ty = threadIdx.y;
    const int s0 = blockIdx.y * 32, d0 = blockIdx.x * 32;
    const float* Vb = V + (size_t)blockIdx.z * SEQ * DIM;
    float* Ob = O + (size_t)blockIdx.z * DIM * SEQ;
#pragma unroll
    for (int j = 0; j < 4; ++j)
        tile[ty + j * 8][tx] = Vb[(size_t)(s0 + ty + j * 8) * DIM + d0 + tx];
    __syncthreads();
#pragma unroll
    for (int j = 0; j < 4; ++j)
        Ob[(size_t)(d0 + ty + j * 8) * SEQ + s0 + tx] = tile[tx][ty + j * 8];
}

// ---------------------------------------------------------------------------
// row softmax over SEQ=1024 (in place, fp32)
// ---------------------------------------------------------------------------
__global__ __launch_bounds__(256)
void softmax_kernel(float* __restrict__ S)
{
    __shared__ float red[8];
    float* row = S + (size_t)blockIdx.x * SEQ;
    const int t = threadIdx.x;

    float4 v = ((float4*)row)[t];
    float m = fmaxf(fmaxf(v.x, v.y), fmaxf(v.z, v.w));
#pragma unroll
    for (int o = 16; o; o >>= 1) m = fmaxf(m, __shfl_xor_sync(0xffffffffu, m, o));
    if ((t & 31) == 0) red[t >> 5] = m;
    __syncthreads();
    float bmax = red[0];
#pragma unroll
    for (int i = 1; i < 8; i++) bmax = fmaxf(bmax, red[i]);
    __syncthreads();

    v.x = __expf(v.x - bmax); v.y = __expf(v.y - bmax);
    v.z = __expf(v.z - bmax); v.w = __expf(v.w - bmax);
    float s = v.x + v.y + v.z + v.w;
#pragma unroll
    for (int o = 16; o; o >>= 1) s += __shfl_xor_sync(0xffffffffu, s, o);
    if ((t & 31) == 0) red[t >> 5] = s;
    __syncthreads();
    float tot = 0.0f;
#pragma unroll
    for (int i = 0; i < 8; i++) tot += red[i];
    const float inv = __frcp_rn(tot);

    v.x *= inv; v.y *= inv; v.z *= inv; v.w *= inv;
    ((float4*)row)[t] = v;
}

// ---------------------------------------------------------------------------
// h = LayerNorm(iA + iB + xC) * gamma + beta   (fp32)
// ---------------------------------------------------------------------------
__global__ __launch_bounds__(256)
void add_ln_kernel(const float* __restrict__ iA, const float* __restrict__ iB,
                   const float* __restrict__ xC,
                   const float* __restrict__ gamma, const float* __restrict__ beta,
                   float* __restrict__ h)
{
    __shared__ float rs[8], rs2[8];
    const size_t base = (size_t)blockIdx.x * DIM;
    const int t = threadIdx.x;

    float x0 = iA[base + t]       + iB[base + t]       + xC[base + t];
    float x1 = iA[base + t + 256] + iB[base + t + 256] + xC[base + t + 256];
    float x2 = iA[base + t + 512] + iB[base + t + 512] + xC[base + t + 512];

    float s  = x0 + x1 + x2;
    float ss = x0 * x0 + x1 * x1 + x2 * x2;
#pragma unroll
    for (int o = 16; o; o >>= 1) {
        s  += __shfl_xor_sync(0xffffffffu, s,  o);
        ss += __shfl_xor_sync(0xffffffffu, ss, o);
    }
    if ((t & 31) == 0) { rs[t >> 5] = s; rs2[t >> 5] = ss; }
    __syncthreads();
    float S1 = 0.0f, S2 = 0.0f;
#pragma unroll
    for (int i = 0; i < 8; i++) { S1 += rs[i]; S2 += rs2[i]; }

    const float mu   = S1 * (1.0f / DIM);
    const float var  = S2 * (1.0f / DIM) - mu * mu;
    const float rstd = rsqrtf(var + EPS);

    h[base + t]       = (x0 - mu) * rstd * gamma[t]       + beta[t];
    h[base + t + 256] = (x1 - mu) * rstd * gamma[t + 256] + beta[t + 256];
    h[base + t + 512] = (x2 - mu) * rstd * gamma[t + 512] + beta[t + 512];
}

// ---------------------------------------------------------------------------
// launch
// ---------------------------------------------------------------------------
extern "C" void kernel_launch(void* const* d_in, const int* in_sizes, int n_in,
                              void* d_out, int out_size)
{
    const float* xA    = (const float*)d_in[0];
    const float* xB    = (const float*)d_in[1];
    const float* xC    = (const float*)d_in[2];
    const float* Wq    = (const float*)d_in[3];
    const float* bq    = (const float*)d_in[4];
    const float* Wk    = (const float*)d_in[5];
    const float* bk    = (const float*)d_in[6];
    const float* Wv    = (const float*)d_in[7];
    const float* bv    = (const float*)d_in[8];
    const float* gamma = (const float*)d_in[9];
    const float* beta  = (const float*)d_in[10];
    const float* Wfc   = (const float*)d_in[11];
    const float* bfc   = (const float*)d_in[12];
    float* out = (float*)d_out;

    float *Q, *KA, *KB, *VA, *VB, *VtA, *VtB, *Sf, *iA, *iB, *h;
    cudaGetSymbolAddress((void**)&Q,   g_Q);
    cudaGetSymbolAddress((void**)&KA,  g_KA);
    cudaGetSymbolAddress((void**)&KB,  g_KB);
    cudaGetSymbolAddress((void**)&VA,  g_VA);
    cudaGetSymbolAddress((void**)&VB,  g_VB);
    cudaGetSymbolAddress((void**)&VtA, g_VtA);
    cudaGetSymbolAddress((void**)&VtB, g_VtB);
    cudaGetSymbolAddress((void**)&Sf,  g_S);
    cudaGetSymbolAddress((void**)&iA,  g_iA);
    cudaGetSymbolAddress((void**)&iB,  g_iB);
    cudaGetSymbolAddress((void**)&h,   g_h);

    cudaFuncSetAttribute(gemm_tf32, cudaFuncAttributeMaxDynamicSharedMemorySize,
                         GEMM_SMEM);

    const float scale = 1.0f / sqrtf((float)DIM);
    const dim3 blk(256);
    const dim3 gproj(DIM / GBN, MTOK / GBM, 1);     // (3, 128)
    const dim3 gqk(SEQ / GBN, SEQ / GBM, BATCH);    // (4, 8, 16)
    const dim3 gpv(DIM / GBN, SEQ / GBM, BATCH);    // (3, 8, 16)
    const long sQK = (long)SEQ * DIM;
    const long sSS = (long)SEQ * SEQ;
    const long sVT = (long)DIM * SEQ;

    // projections: X @ W^T + b   (K = 768)
    gemm_tf32<<<gproj, blk, GEMM_SMEM>>>(xC, 0, Wq, 0, DIM, Q,  DIM, 0, bq, 1.0f);
    gemm_tf32<<<gproj, blk, GEMM_SMEM>>>(xA, 0, Wk, 0, DIM, KA, DIM, 0, bk, 1.0f);
    gemm_tf32<<<gproj, blk, GEMM_SMEM>>>(xB, 0, Wk, 0, DIM, KB, DIM, 0, bk, 1.0f);
    gemm_tf32<<<gproj, blk, GEMM_SMEM>>>(xA, 0, Wv, 0, DIM, VA, DIM, 0, bv, 1.0f);
    gemm_tf32<<<gproj, blk, GEMM_SMEM>>>(xB, 0, Wv, 0, DIM, VB, DIM, 0, bv, 1.0f);

    // V transposes
    const dim3 tblk(32, 8);
    const dim3 tgrid(DIM / 32, SEQ / 32, BATCH);
    transpose_kernel<<<tgrid, tblk>>>(VA, VtA);
    transpose_kernel<<<tgrid, tblk>>>(VB, VtB);

    // branch A: S = softmax(scale * Q K^T); iA = S @ V_A
    gemm_tf32<<<gqk, blk, GEMM_SMEM>>>(Q, sQK, KA, sQK, DIM, Sf, SEQ, sSS, nullptr, scale);
    softmax_kernel<<<BATCH * SEQ, blk>>>(Sf);
    gemm_tf32<<<gpv, blk, GEMM_SMEM>>>(Sf, sSS, VtA, sVT, SEQ, iA, DIM, sQK, nullptr, 1.0f);

    // branch B
    gemm_tf32<<<gqk, blk, GEMM_SMEM>>>(Q, sQK, KB, sQK, DIM, Sf, SEQ, sSS, nullptr, scale);
    softmax_kernel<<<BATCH * SEQ, blk>>>(Sf);
    gemm_tf32<<<gpv, blk, GEMM_SMEM>>>(Sf, sSS, VtB, sVT, SEQ, iB, DIM, sQK, nullptr, 1.0f);

    // residual + LN + final FC
    add_ln_kernel<<<MTOK, blk>>>(iA, iB, xC, gamma, beta, h);
    gemm_tf32<<<gproj, blk, GEMM_SMEM>>>(h, 0, Wfc, 0, DIM, out, DIM, 0, bfc, 1.0f);
}